// round 3
// baseline (speedup 1.0000x reference)
#include <cuda_runtime.h>

// Bilinear resample: B=16, S=128, C=128, fp32.
// R3: 4 pixels per warp-iteration (16 independent 512B gathers in flight),
// grid-stride loop over pixel-quads to avoid block launch churn.

#define S 128
#define C 128
#define C4 (C / 4)           // float4s per pixel row
#define NPIX (16 * S * S)    // 262144
#define NQUAD (NPIX / 4)     // 65536

__global__ __launch_bounds__(256) void resample_kernel(
    const float* __restrict__ offsets,
    const float* __restrict__ inputs,
    float* __restrict__ out)
{
    const int lane = threadIdx.x & 31;
    const int warpInBlock = threadIdx.x >> 5;
    const int nwarps = gridDim.x * (blockDim.x >> 5);
    int w = blockIdx.x * (blockDim.x >> 5) + warpInBlock;

    const float4* off4 = reinterpret_cast<const float4*>(offsets);
    const float4* in4  = reinterpret_cast<const float4*>(inputs);
    float4*       out4 = reinterpret_cast<float4*>(out);

    for (int q = w; q < NQUAD; q += nwarps) {
        const int pix0 = q * 4;
        const int j0 = pix0 & (S - 1);          // col of pixel 0 (multiple of 4)
        const int i  = (pix0 >> 7) & (S - 1);   // row (shared by all 4 pixels)
        const int b  = pix0 >> 14;              // batch (shared)

        // 32B of offsets = 4 pixels' (dy,dx) pairs; broadcast loads.
        const float4 offA = __ldg(off4 + q * 2);
        const float4 offB = __ldg(off4 + q * 2 + 1);

        const float oy[4] = { offA.x, offA.z, offB.x, offB.z };
        const float ox[4] = { offA.y, offA.w, offB.y, offB.w };

        int p00[4], p01[4], p10[4], p11[4];
        float fy[4], fx[4];
        const float4* base = in4 + (size_t)b * (S * S * C4);

#pragma unroll
        for (int k = 0; k < 4; k++) {
            const float y = fminf(fmaxf(oy[k] + (float)i,        0.0f), (float)(S - 1));
            const float x = fminf(fmaxf(ox[k] + (float)(j0 + k), 0.0f), (float)(S - 1));
            const float y0f = floorf(y);
            const float x0f = floorf(x);
            const int y0 = (int)y0f;
            const int x0 = (int)x0f;
            const int y1 = (int)ceilf(y);
            const int x1 = (int)ceilf(x);
            fy[k] = y - y0f;          // row fraction
            fx[k] = x - x0f;          // col fraction
            p00[k] = (y0 * S + x0) * C4 + lane;
            p01[k] = (y0 * S + x1) * C4 + lane;
            p10[k] = (y1 * S + x0) * C4 + lane;
            p11[k] = (y1 * S + x1) * C4 + lane;
        }

        // 16 independent coalesced 512B gathers — front-batched for MLP.
        float4 v00[4], v01[4], v10[4], v11[4];
#pragma unroll
        for (int k = 0; k < 4; k++) {
            v00[k] = __ldg(base + p00[k]);
            v01[k] = __ldg(base + p01[k]);
            v10[k] = __ldg(base + p10[k]);
            v11[k] = __ldg(base + p11[k]);
        }

        float4* outp = out4 + (size_t)pix0 * C4 + lane;
#pragma unroll
        for (int k = 0; k < 4; k++) {
            // t = lt + (rt-lt)*fcol ; bo = lb + (rb-lb)*fcol ; o = t + (bo-t)*frow
            float4 t, bo, o;
            t.x  = v00[k].x + (v01[k].x - v00[k].x) * fx[k];
            t.y  = v00[k].y + (v01[k].y - v00[k].y) * fx[k];
            t.z  = v00[k].z + (v01[k].z - v00[k].z) * fx[k];
            t.w  = v00[k].w + (v01[k].w - v00[k].w) * fx[k];
            bo.x = v10[k].x + (v11[k].x - v10[k].x) * fx[k];
            bo.y = v10[k].y + (v11[k].y - v10[k].y) * fx[k];
            bo.z = v10[k].z + (v11[k].z - v10[k].z) * fx[k];
            bo.w = v10[k].w + (v11[k].w - v10[k].w) * fx[k];
            o.x  = t.x + (bo.x - t.x) * fy[k];
            o.y  = t.y + (bo.y - t.y) * fy[k];
            o.z  = t.z + (bo.z - t.z) * fy[k];
            o.w  = t.w + (bo.w - t.w) * fy[k];
            outp[k * C4] = o;
        }
    }
}

extern "C" void kernel_launch(void* const* d_in, const int* in_sizes, int n_in,
                              void* d_out, int out_size)
{
    const float* offsets = (const float*)d_in[0];
    const float* inputs  = (const float*)d_in[1];
    float* out = (float*)d_out;

    const int threads = 256;
    const int blocks  = 1184;   // 148 SMs * 8 CTAs nominal; grid-stride covers all
    resample_kernel<<<blocks, threads>>>(offsets, inputs, out);
}